// round 16
// baseline (speedup 1.0000x reference)
#include <cuda_runtime.h>
#include <cuda_fp16.h>
#include <cuda_pipeline.h>
#include <math_constants.h>
#include <mma.h>

using namespace nvcuda;

// Problem shape (fixed per reference)
constexpr int Bb = 4;
constexpr int Ss = 2048;
constexpr int Dd = 1024;
constexpr long long QKV_E = (long long)Bb * Ss * Dd;       // 8,388,608
constexpr long long ATT_E = (long long)Bb * Ss * Ss;       // 16,777,216
constexpr long long QKV3_E = (long long)Bb * Ss * 3 * Dd;  // 25,165,824

// ---- static scratch (no cudaMalloc anywhere) ----
__device__ __half g_inp_h [QKV_E];
__device__ __half g_wqkv_t[(long long)3 * Dd * Dd];   // rows: [Wq^T; Wk^T; Wv^T]
__device__ __half g_wo_t  [(long long)Dd * Dd];
__device__ __half g_qkv_h [QKV3_E];                   // [B*S, 3*D]  (q | k | v)
__device__ __half g_att_h [ATT_E];                    // exp(score/32), masked, fp16
__device__ __half g_ctx_h [QKV_E];
__device__ float  g_inv   [Bb * Ss];                  // 1 / row sum of exps

// device-side buffer selector
__device__ __forceinline__ __half* hbuf(int id)
{
    switch (id) {
        case 0:  return g_inp_h;
        case 1:  return g_wqkv_t;
        case 2:  return g_wo_t;
        case 3:  return g_qkv_h;
        case 4:  return g_att_h;
        default: return g_ctx_h;
    }
}

// ---------------------------------------------------------------------------
// HGEMM body (round-13 mainloop).
//   BNN=false: C = A[M,K] * Bt[N,K]^T ; BNN=true: C = A[M,K] * B[K,N]
// Block 128x128x64, 4 warps (2x2), warp tile 64x64, A-fragment double
// buffering + B streamed one ahead, 3-stage cp.async pipeline, (128,2).
//   EPI: 1 = fp16 staged (SCALEROW: multiply row by g_inv before convert)
//        2 = fp32 + fused bias staged
//        3 = exp(score*1/32) with causal mask, fp16 staged (scores)
//   KLIM : K loop limited to row0+128
// ---------------------------------------------------------------------------
#define TBM 128
#define TBN 128
#define TBK 64
#define TPAD 72                                         // TBK + 8
#define BPAD 136                                        // TBN + 8 (NN B tiles)
#define NSTAGE 3
#define STAGE_A_HALVES (TBM * TPAD)                     // 9216
#define STAGE_B_HALVES (TBM * TPAD)                     // 9216 (>= 64*136=8704)
#define SMEM_TOTAL (NSTAGE * (STAGE_A_HALVES + STAGE_B_HALVES) * 2)   // 110592
#define STAGE_FLOATS_PER_WARP 320                       // 16 x 20

template <int EPI, bool KLIM, bool BNN, bool SCALEROW>
__device__ __forceinline__ void hgemm_body(
    int row0, int col0, long long bz,
    int aId, long long aOff, int bId, long long bOff,
    int cId, long long cOff, float* extC, const float* bias,
    int K, int lda, int ldb, int ldc,
    long long strA, long long strB, long long strC,
    char* dynbuf)
{
    int Keff = K;
    if (KLIM) {
        int lim = row0 + TBM;
        if (lim < K) Keff = lim;
    }

    const __half* Ap = hbuf(aId) + aOff + bz * strA + (long long)row0 * lda;
    const __half* Bp = hbuf(bId) + bOff + bz * strB
                     + (BNN ? (long long)col0 : (long long)col0 * ldb);

    __half* sAbase = reinterpret_cast<__half*>(dynbuf);
    __half* sBbase = sAbase + NSTAGE * STAGE_A_HALVES;

    const int tid  = threadIdx.x;
    const int warp = tid >> 5;
    const int lane = tid & 31;
    const int wm   = warp & 1;     // 0..1 : 64-row strip
    const int wn   = warp >> 1;    // 0..1 : 64-col strip

    wmma::fragment<wmma::accumulator, 16, 16, 16, float> acc[4][4];
#pragma unroll
    for (int i = 0; i < 4; i++) {
#pragma unroll
        for (int j = 0; j < 4; j++) {
            wmma::fill_fragment(acc[i][j], 0.0f);
        }
    }

    const int iters = Keff / TBK;

    // prologue: prefetch stages 0 .. NSTAGE-2  (128 threads, 8 chunks each)
#pragma unroll
    for (int s = 0; s < NSTAGE - 1; s++) {
        if (s < iters) {
            const int k0 = s * TBK;
            __half* sA = sAbase + s * STAGE_A_HALVES;
            __half* sB = sBbase + s * STAGE_B_HALVES;
#pragma unroll
            for (int p = 0; p < 8; p++) {
                int ch = tid + p * 128;
                int r = ch >> 3;
                int c = (ch & 7) * 8;
                __pipeline_memcpy_async(&sA[r * TPAD + c], Ap + (long long)r * lda + k0 + c, 16);
            }
            if (BNN) {
#pragma unroll
                for (int p = 0; p < 8; p++) {
                    int ch = tid + p * 128;
                    int r = ch >> 4;
                    int c = (ch & 15) * 8;
                    __pipeline_memcpy_async(&sB[r * BPAD + c], Bp + (long long)(k0 + r) * ldb + c, 16);
                }
            } else {
#pragma unroll
                for (int p = 0; p < 8; p++) {
                    int ch = tid + p * 128;
                    int r = ch >> 3;
                    int c = (ch & 7) * 8;
                    __pipeline_memcpy_async(&sB[r * TPAD + c], Bp + (long long)r * ldb + k0 + c, 16);
                }
            }
        }
        __pipeline_commit();
    }

    for (int it = 0; it < iters; ++it) {
        __pipeline_wait_prior(NSTAGE - 2);
        __syncthreads();

        const int cur = it % NSTAGE;
        const __half* sAc = sAbase + cur * STAGE_A_HALVES;
        const __half* sBc = sBbase + cur * STAGE_B_HALVES;

        const int ldIt = it + NSTAGE - 1;
        if (ldIt < iters) {
            const int s = ldIt % NSTAGE;
            const int k0 = ldIt * TBK;
            __half* sA = sAbase + s * STAGE_A_HALVES;
            __half* sB = sBbase + s * STAGE_B_HALVES;
#pragma unroll
            for (int p = 0; p < 8; p++) {
                int ch = tid + p * 128;
                int r = ch >> 3;
                int c = (ch & 7) * 8;
                __pipeline_memcpy_async(&sA[r * TPAD + c], Ap + (long long)r * lda + k0 + c, 16);
            }
            if (BNN) {
#pragma unroll
                for (int p = 0; p < 8; p++) {
                    int ch = tid + p * 128;
                    int r = ch >> 4;
                    int c = (ch & 15) * 8;
                    __pipeline_memcpy_async(&sB[r * BPAD + c], Bp + (long long)(k0 + r) * ldb + c, 16);
                }
            } else {
#pragma unroll
                for (int p = 0; p < 8; p++) {
                    int ch = tid + p * 128;
                    int r = ch >> 3;
                    int c = (ch & 7) * 8;
                    __pipeline_memcpy_async(&sB[r * TPAD + c], Bp + (long long)r * ldb + k0 + c, 16);
                }
            }
        }
        __pipeline_commit();

        // ---- software-pipelined compute over 4 k16 steps ----
        wmma::fragment<wmma::matrix_a, 16, 16, 16, __half, wmma::row_major> afb[2][4];
#pragma unroll
        for (int mf = 0; mf < 4; mf++) {
            wmma::load_matrix_sync(afb[0][mf], &sAc[(wm * 64 + mf * 16) * TPAD + 0], TPAD);
        }

#pragma unroll
        for (int s = 0; s < 4; ++s) {
            const int kk = s * 16;
            if (s < 3) {
#pragma unroll
                for (int mf = 0; mf < 4; mf++) {
                    wmma::load_matrix_sync(afb[(s + 1) & 1][mf],
                                           &sAc[(wm * 64 + mf * 16) * TPAD + kk + 16], TPAD);
                }
            }
            if (BNN) {
                wmma::fragment<wmma::matrix_b, 16, 16, 16, __half, wmma::row_major> bfp[2];
                wmma::load_matrix_sync(bfp[0], &sBc[kk * BPAD + wn * 64 + 0], BPAD);
#pragma unroll
                for (int nf = 0; nf < 4; nf++) {
                    if (nf < 3) {
                        wmma::load_matrix_sync(bfp[(nf + 1) & 1],
                                               &sBc[kk * BPAD + wn * 64 + (nf + 1) * 16], BPAD);
                    }
#pragma unroll
                    for (int mf = 0; mf < 4; mf++) {
                        wmma::mma_sync(acc[mf][nf], afb[s & 1][mf], bfp[nf & 1], acc[mf][nf]);
                    }
                }
            } else {
                wmma::fragment<wmma::matrix_b, 16, 16, 16, __half, wmma::col_major> bfp[2];
                wmma::load_matrix_sync(bfp[0], &sBc[(wn * 64 + 0) * TPAD + kk], TPAD);
#pragma unroll
                for (int nf = 0; nf < 4; nf++) {
                    if (nf < 3) {
                        wmma::load_matrix_sync(bfp[(nf + 1) & 1],
                                               &sBc[(wn * 64 + (nf + 1) * 16) * TPAD + kk], TPAD);
                    }
#pragma unroll
                    for (int mf = 0; mf < 4; mf++) {
                        wmma::mma_sync(acc[mf][nf], afb[s & 1][mf], bfp[nf & 1], acc[mf][nf]);
                    }
                }
            }
        }
    }

    // ---- staged epilogues (all paths) ----
    __pipeline_wait_prior(0);
    __syncthreads();
    float* ws = reinterpret_cast<float*>(dynbuf) + warp * STAGE_FLOATS_PER_WARP;

    if (EPI == 1) {
        __half* Ch = hbuf(cId) + cOff + bz * strC;
#pragma unroll
        for (int mf = 0; mf < 4; mf++) {
#pragma unroll
            for (int nf = 0; nf < 4; nf++) {
                __syncwarp();
                wmma::store_matrix_sync(ws, acc[mf][nf], 20, wmma::mem_row_major);
                __syncwarp();
                int r0 = row0 + wm * 64 + mf * 16;
                int c0 = col0 + wn * 64 + nf * 16;
#pragma unroll
                for (int e = 0; e < 4; e++) {
                    int idx = lane * 4 + e;        // 0..127
                    int r = idx >> 3;              // 0..15
                    int c2 = idx & 7;              // 0..7
                    float f0 = ws[r * 20 + c2 * 2];
                    float f1 = ws[r * 20 + c2 * 2 + 1];
                    if (SCALEROW) {
                        float iv = g_inv[bz * Ss + r0 + r];
                        f0 *= iv;
                        f1 *= iv;
                    }
                    *reinterpret_cast<__half2*>(&Ch[(long long)(r0 + r) * ldc + c0 + c2 * 2]) =
                        __floats2half2_rn(f0, f1);
                }
            }
        }
        return;
    }

    if (EPI == 3) {
        // scores: write exp(score/32) with causal mask, fp16
        __half* Ch = hbuf(cId) + cOff + bz * strC;
        const float scl = 0.03125f;   // 1/sqrt(1024)
#pragma unroll
        for (int mf = 0; mf < 4; mf++) {
#pragma unroll
            for (int nf = 0; nf < 4; nf++) {
                __syncwarp();
                wmma::store_matrix_sync(ws, acc[mf][nf], 20, wmma::mem_row_major);
                __syncwarp();
                int r0 = row0 + wm * 64 + mf * 16;
                int c0 = col0 + wn * 64 + nf * 16;
#pragma unroll
                for (int e = 0; e < 4; e++) {
                    int idx = lane * 4 + e;
                    int r = idx >> 3;
                    int c2 = idx & 7;
                    int gr = r0 + r;
                    int gc = c0 + c2 * 2;
                    float f0 = ws[r * 20 + c2 * 2];
                    float f1 = ws[r * 20 + c2 * 2 + 1];
                    float e0 = (gc <= gr) ? __expf(f0 * scl) : 0.0f;
                    float e1 = (gc + 1 <= gr) ? __expf(f1 * scl) : 0.0f;
                    *reinterpret_cast<__half2*>(&Ch[(long long)gr * ldc + gc]) =
                        __floats2half2_rn(e0, e1);
                }
            }
        }
        return;
    }

    // EPI == 2: fp32 store with fused bias
    {
        float* Cp = extC + bz * strC;
#pragma unroll
        for (int mf = 0; mf < 4; mf++) {
#pragma unroll
            for (int nf = 0; nf < 4; nf++) {
                __syncwarp();
                wmma::store_matrix_sync(ws, acc[mf][nf], 20, wmma::mem_row_major);
                __syncwarp();
                int r0 = row0 + wm * 64 + mf * 16;
                int c0 = col0 + wn * 64 + nf * 16;
#pragma unroll
                for (int e = 0; e < 8; e++) {
                    int idx = lane + e * 32;       // 0..255
                    int r = idx >> 4;              // 0..15
                    int c = idx & 15;              // 0..15
                    Cp[(long long)(r0 + r) * ldc + c0 + c] = ws[r * 20 + c] + bias[c0 + c];
                }
            }
        }
    }
}

// standalone GEMM launches (QK proj / ctx / out)
template <int EPI, bool KLIM, bool BNN, bool SCALEROW>
__global__ void __launch_bounds__(128, 2)
hgemm_kernel(int aId, long long aOff, int bId, long long bOff,
             int cId, long long cOff, float* extC, const float* bias,
             int K, int lda, int ldb, int ldc,
             long long strA, long long strB, long long strC)
{
    extern __shared__ __align__(16) char dynbuf[];
    hgemm_body<EPI, KLIM, BNN, SCALEROW>(blockIdx.y * TBM, blockIdx.x * TBN, blockIdx.z,
                                         aId, aOff, bId, bOff, cId, cOff, extC, bias,
                                         K, lda, ldb, ldc, strA, strB, strC, dynbuf);
}

// fused launch: z<4 -> causal scores tiles (exp epilogue); z==4 -> V proj
__global__ void __launch_bounds__(128, 2)
fused_sv_kernel()
{
    extern __shared__ __align__(16) char dynbuf[];
    const long long sQ3 = (long long)Ss * 3 * Dd;
    const long long sAT = (long long)Ss * Ss;

    if (blockIdx.z < 4) {
        // scores -> exp(score/32) masked fp16 into g_att_h
        if (blockIdx.y >= (unsigned)(Ss / TBM)) return;
        const int row0 = blockIdx.y * TBM;
        const int col0 = blockIdx.x * TBN;
        if (col0 > row0 + TBM - 1) return;          // causal tile skip
        hgemm_body<3, false, false, false>(row0, col0, (long long)blockIdx.z,
                                           3, 0, 3, Dd, 4, 0, (float*)0, (const float*)0,
                                           Dd, 3 * Dd, 3 * Dd, Ss, sQ3, sQ3, sAT, dynbuf);
    } else {
        // V projection: inp * Wv^T -> qkv cols [2048, 3072)
        if (blockIdx.x >= (unsigned)(Dd / TBN)) return;
        hgemm_body<1, false, false, false>(blockIdx.y * TBM, blockIdx.x * TBN, 0,
                                           0, 0, 1, (long long)2 * Dd * Dd,
                                           3, (long long)2 * Dd, (float*)0, (const float*)0,
                                           Dd, Dd, Dd, 3 * Dd, 0, 0, 0, dynbuf);
    }
}

// ---------------------------------------------------------------------------
// conversions / transposes
// ---------------------------------------------------------------------------
__global__ void conv_inp_kernel(const float* __restrict__ in)
{
    long long i = ((long long)blockIdx.x * 256 + threadIdx.x) * 4;
    if (i < QKV_E) {
        float4 v = *reinterpret_cast<const float4*>(in + i);
        __half2* o = reinterpret_cast<__half2*>(g_inp_h + i);
        o[0] = __floats2half2_rn(v.x, v.y);
        o[1] = __floats2half2_rn(v.z, v.w);
    }
}

// fused weight transpose: z in {0,1,2} -> g_wqkv_t slab, z==3 -> g_wo_t
__global__ void wtrans4_kernel(const float* __restrict__ w0, const float* __restrict__ w1,
                               const float* __restrict__ w2, const float* __restrict__ w3)
{
    __shared__ float t[32][33];
    const float* in;
    __half* out;
    if (blockIdx.z == 0)      { in = w0; out = g_wqkv_t; }
    else if (blockIdx.z == 1) { in = w1; out = g_wqkv_t + (long long)Dd * Dd; }
    else if (blockIdx.z == 2) { in = w2; out = g_wqkv_t + (long long)2 * Dd * Dd; }
    else                      { in = w3; out = g_wo_t; }
    int r0 = blockIdx.y * 32;
    int c0 = blockIdx.x * 32;
    for (int i = threadIdx.y; i < 32; i += 8) {
        t[i][threadIdx.x] = in[(long long)(r0 + i) * Dd + c0 + threadIdx.x];
    }
    __syncthreads();
    for (int i = threadIdx.y; i < 32; i += 8) {
        out[(long long)(c0 + i) * Dd + r0 + threadIdx.x] = __float2half(t[threadIdx.x][i]);
    }
}

// ---------------------------------------------------------------------------
// Row-sum of exp values (fp16) -> inverse, per (q, b) row.
// ---------------------------------------------------------------------------
__global__ void __launch_bounds__(256)
rowsum_kernel()
{
    const int q = blockIdx.x;
    const int b = blockIdx.y;
    const __half* row = g_att_h + ((long long)b * Ss + q) * (long long)Ss;
    const int n = q + 1;
    const int tid = threadIdx.x;

    __shared__ float sred[8];

    float s = 0.0f;
    for (int j = tid; j < n; j += 256) {
        s += __half2float(row[j]);
    }
    for (int o = 16; o; o >>= 1) {
        s += __shfl_xor_sync(0xffffffffu, s, o);
    }
    if ((tid & 31) == 0) sred[tid >> 5] = s;
    __syncthreads();
    if (tid == 0) {
        float v = sred[0];
        for (int w = 1; w < 8; w++) v += sred[w];
        g_inv[b * Ss + q] = 1.0f / v;
    }
}

// ---------------------------------------------------------------------------
extern "C" void kernel_launch(void* const* d_in, const int* in_sizes, int n_in,
                              void* d_out, int out_size)
{
    const float* inp = (const float*)d_in[0];
    const float* Wq  = (const float*)d_in[1];
    const float* Wk  = (const float*)d_in[2];
    const float* Wv  = (const float*)d_in[3];
    const float* Wo  = (const float*)d_in[4];
    const float* bo  = (const float*)d_in[5];
    float* out = (float*)d_out;

    const int M = Bb * Ss;                           // 8192
    const long long sQ3 = (long long)Ss * 3 * Dd;    // per-batch stride, qkv buffer
    const long long sQK = (long long)Ss * Dd;        // per-batch q/k/v-sized stride
    const long long sAT = (long long)Ss * Ss;        // per-batch attn stride

    cudaFuncSetAttribute(hgemm_kernel<1, false, false, false>, cudaFuncAttributeMaxDynamicSharedMemorySize, SMEM_TOTAL);
    cudaFuncSetAttribute(hgemm_kernel<1, true,  true,  true >, cudaFuncAttributeMaxDynamicSharedMemorySize, SMEM_TOTAL);
    cudaFuncSetAttribute(hgemm_kernel<2, false, false, false>, cudaFuncAttributeMaxDynamicSharedMemorySize, SMEM_TOTAL);
    cudaFuncSetAttribute(fused_sv_kernel, cudaFuncAttributeMaxDynamicSharedMemorySize, SMEM_TOTAL);

    const unsigned nConv = (unsigned)((QKV_E / 4 + 255) / 256);
    dim3 tb(32, 8);

    // fp32 -> fp16 input; all 4 weights transposed in one launch
    conv_inp_kernel<<<nConv, 256>>>(inp);
    dim3 tw(Dd / 32, Dd / 32, 4);
    wtrans4_kernel<<<tw, tb>>>(Wq, Wk, Wv, Wo);

    // 1) QK projection: [8192,1024] x [2048,1024]^T -> qkv cols [0,2048)
    dim3 gQK(2 * Dd / TBN, M / TBM, 1);
    hgemm_kernel<1, false, false, false><<<gQK, 128, SMEM_TOTAL>>>(
        0, 0, 1, 0, 3, 0, (float*)0, (const float*)0,
        Dd, Dd, Dd, 3 * Dd, 0, 0, 0);

    // 2) fused: scores -> masked exp fp16 (z<4) + V projection (z==4)
    dim3 gF(Ss / TBN, M / TBM, 5);
    fused_sv_kernel<<<gF, 128, SMEM_TOTAL>>>();

    // 3) row sums of exps -> g_inv
    dim3 gRs(Ss, Bb);
    rowsum_kernel<<<gRs, 256>>>();

    // 4) ctx = P_unnorm * V per batch (K limited), row-normalized in epilogue
    dim3 gCtx(Dd / TBN, Ss / TBM, Bb);
    hgemm_kernel<1, true, true, true><<<gCtx, 128, SMEM_TOTAL>>>(
        4, 0, 3, 2 * Dd, 5, 0, (float*)0, (const float*)0,
        Ss, Ss, 3 * Dd, Dd, sAT, sQ3, sQK);

    // 5) out = ctx * W_o + b_o (fused bias in epilogue)
    dim3 gOut(Dd / TBN, M / TBM, 1);
    hgemm_kernel<2, false, false, false><<<gOut, 128, SMEM_TOTAL>>>(
        5, 0, 2, 0, -1, 0, out, bo,
        Dd, Dd, Dd, Dd, 0, 0, 0);
}

// round 17
// speedup vs baseline: 1.0280x; 1.0280x over previous
#include <cuda_runtime.h>
#include <cuda_fp16.h>
#include <cuda_pipeline.h>
#include <math_constants.h>
#include <mma.h>

using namespace nvcuda;

// Problem shape (fixed per reference)
constexpr int Bb = 4;
constexpr int Ss = 2048;
constexpr int Dd = 1024;
constexpr long long QKV_E = (long long)Bb * Ss * Dd;       // 8,388,608
constexpr long long ATT_E = (long long)Bb * Ss * Ss;       // 16,777,216
constexpr long long QKV3_E = (long long)Bb * Ss * 3 * Dd;  // 25,165,824

// ---- static scratch (no cudaMalloc anywhere) ----
__device__ __half g_inp_h [QKV_E];
__device__ __half g_wqkv_t[(long long)3 * Dd * Dd];   // rows: [Wq^T; Wk^T; Wv^T]
__device__ __half g_wo_t  [(long long)Dd * Dd];
__device__ __half g_qkv_h [QKV3_E];                   // [B*S, 3*D]  (q | k | v)
__device__ __half g_att_h [ATT_E];                    // exp(score/32), masked, fp16
__device__ __half g_ctx_h [QKV_E];
__device__ float  g_sum   [Bb * Ss];                  // row sums of exps (atomic)

// device-side buffer selector
__device__ __forceinline__ __half* hbuf(int id)
{
    switch (id) {
        case 0:  return g_inp_h;
        case 1:  return g_wqkv_t;
        case 2:  return g_wo_t;
        case 3:  return g_qkv_h;
        case 4:  return g_att_h;
        default: return g_ctx_h;
    }
}

// ---------------------------------------------------------------------------
// HGEMM body (round-13 mainloop).
//   BNN=false: C = A[M,K] * Bt[N,K]^T ; BNN=true: C = A[M,K] * B[K,N]
// Block 128x128x64, 4 warps (2x2), warp tile 64x64, A-fragment double
// buffering + B streamed one ahead, 3-stage cp.async pipeline, (128,2).
//   EPI: 1 = fp16 staged (SCALEROW: divide row by g_sum before convert)
//        2 = fp32 + fused bias staged
//        3 = exp(score/32) with causal mask, fp16 staged, PLUS per-row
//            atomicAdd partial sums into g_sum (fused rowsum)
//   KLIM : K loop limited to row0+128
// ---------------------------------------------------------------------------
#define TBM 128
#define TBN 128
#define TBK 64
#define TPAD 72                                         // TBK + 8
#define BPAD 136                                        // TBN + 8 (NN B tiles)
#define NSTAGE 3
#define STAGE_A_HALVES (TBM * TPAD)                     // 9216
#define STAGE_B_HALVES (TBM * TPAD)                     // 9216 (>= 64*136=8704)
#define SMEM_TOTAL (NSTAGE * (STAGE_A_HALVES + STAGE_B_HALVES) * 2)   // 110592
#define STAGE_FLOATS_PER_WARP 320                       // 16 x 20

template <int EPI, bool KLIM, bool BNN, bool SCALEROW>
__device__ __forceinline__ void hgemm_body(
    int row0, int col0, long long bz,
    int aId, long long aOff, int bId, long long bOff,
    int cId, long long cOff, float* extC, const float* bias,
    int K, int lda, int ldb, int ldc,
    long long strA, long long strB, long long strC,
    char* dynbuf)
{
    int Keff = K;
    if (KLIM) {
        int lim = row0 + TBM;
        if (lim < K) Keff = lim;
    }

    const __half* Ap = hbuf(aId) + aOff + bz * strA + (long long)row0 * lda;
    const __half* Bp = hbuf(bId) + bOff + bz * strB
                     + (BNN ? (long long)col0 : (long long)col0 * ldb);

    __half* sAbase = reinterpret_cast<__half*>(dynbuf);
    __half* sBbase = sAbase + NSTAGE * STAGE_A_HALVES;

    const int tid  = threadIdx.x;
    const int warp = tid >> 5;
    const int lane = tid & 31;
    const int wm   = warp & 1;     // 0..1 : 64-row strip
    const int wn   = warp >> 1;    // 0..1 : 64-col strip

    wmma::fragment<wmma::accumulator, 16, 16, 16, float> acc[4][4];
#pragma unroll
    for (int i = 0; i < 4; i++) {
#pragma unroll
        for (int j = 0; j < 4; j++) {
            wmma::fill_fragment(acc[i][j], 0.0f);
        }
    }

    const int iters = Keff / TBK;

    // prologue: prefetch stages 0 .. NSTAGE-2  (128 threads, 8 chunks each)
#pragma unroll
    for (int s = 0; s < NSTAGE - 1; s++) {
        if (s < iters) {
            const int k0 = s * TBK;
            __half* sA = sAbase + s * STAGE_A_HALVES;
            __half* sB = sBbase + s * STAGE_B_HALVES;
#pragma unroll
            for (int p = 0; p < 8; p++) {
                int ch = tid + p * 128;
                int r = ch >> 3;
                int c = (ch & 7) * 8;
                __pipeline_memcpy_async(&sA[r * TPAD + c], Ap + (long long)r * lda + k0 + c, 16);
            }
            if (BNN) {
#pragma unroll
                for (int p = 0; p < 8; p++) {
                    int ch = tid + p * 128;
                    int r = ch >> 4;
                    int c = (ch & 15) * 8;
                    __pipeline_memcpy_async(&sB[r * BPAD + c], Bp + (long long)(k0 + r) * ldb + c, 16);
                }
            } else {
#pragma unroll
                for (int p = 0; p < 8; p++) {
                    int ch = tid + p * 128;
                    int r = ch >> 3;
                    int c = (ch & 7) * 8;
                    __pipeline_memcpy_async(&sB[r * TPAD + c], Bp + (long long)r * ldb + k0 + c, 16);
                }
            }
        }
        __pipeline_commit();
    }

    for (int it = 0; it < iters; ++it) {
        __pipeline_wait_prior(NSTAGE - 2);
        __syncthreads();

        const int cur = it % NSTAGE;
        const __half* sAc = sAbase + cur * STAGE_A_HALVES;
        const __half* sBc = sBbase + cur * STAGE_B_HALVES;

        const int ldIt = it + NSTAGE - 1;
        if (ldIt < iters) {
            const int s = ldIt % NSTAGE;
            const int k0 = ldIt * TBK;
            __half* sA = sAbase + s * STAGE_A_HALVES;
            __half* sB = sBbase + s * STAGE_B_HALVES;
#pragma unroll
            for (int p = 0; p < 8; p++) {
                int ch = tid + p * 128;
                int r = ch >> 3;
                int c = (ch & 7) * 8;
                __pipeline_memcpy_async(&sA[r * TPAD + c], Ap + (long long)r * lda + k0 + c, 16);
            }
            if (BNN) {
#pragma unroll
                for (int p = 0; p < 8; p++) {
                    int ch = tid + p * 128;
                    int r = ch >> 4;
                    int c = (ch & 15) * 8;
                    __pipeline_memcpy_async(&sB[r * BPAD + c], Bp + (long long)(k0 + r) * ldb + c, 16);
                }
            } else {
#pragma unroll
                for (int p = 0; p < 8; p++) {
                    int ch = tid + p * 128;
                    int r = ch >> 3;
                    int c = (ch & 7) * 8;
                    __pipeline_memcpy_async(&sB[r * TPAD + c], Bp + (long long)r * ldb + k0 + c, 16);
                }
            }
        }
        __pipeline_commit();

        // ---- software-pipelined compute over 4 k16 steps ----
        wmma::fragment<wmma::matrix_a, 16, 16, 16, __half, wmma::row_major> afb[2][4];
#pragma unroll
        for (int mf = 0; mf < 4; mf++) {
            wmma::load_matrix_sync(afb[0][mf], &sAc[(wm * 64 + mf * 16) * TPAD + 0], TPAD);
        }

#pragma unroll
        for (int s = 0; s < 4; ++s) {
            const int kk = s * 16;
            if (s < 3) {
#pragma unroll
                for (int mf = 0; mf < 4; mf++) {
                    wmma::load_matrix_sync(afb[(s + 1) & 1][mf],
                                           &sAc[(wm * 64 + mf * 16) * TPAD + kk + 16], TPAD);
                }
            }
            if (BNN) {
                wmma::fragment<wmma::matrix_b, 16, 16, 16, __half, wmma::row_major> bfp[2];
                wmma::load_matrix_sync(bfp[0], &sBc[kk * BPAD + wn * 64 + 0], BPAD);
#pragma unroll
                for (int nf = 0; nf < 4; nf++) {
                    if (nf < 3) {
                        wmma::load_matrix_sync(bfp[(nf + 1) & 1],
                                               &sBc[kk * BPAD + wn * 64 + (nf + 1) * 16], BPAD);
                    }
#pragma unroll
                    for (int mf = 0; mf < 4; mf++) {
                        wmma::mma_sync(acc[mf][nf], afb[s & 1][mf], bfp[nf & 1], acc[mf][nf]);
                    }
                }
            } else {
                wmma::fragment<wmma::matrix_b, 16, 16, 16, __half, wmma::col_major> bfp[2];
                wmma::load_matrix_sync(bfp[0], &sBc[(wn * 64 + 0) * TPAD + kk], TPAD);
#pragma unroll
                for (int nf = 0; nf < 4; nf++) {
                    if (nf < 3) {
                        wmma::load_matrix_sync(bfp[(nf + 1) & 1],
                                               &sBc[(wn * 64 + (nf + 1) * 16) * TPAD + kk], TPAD);
                    }
#pragma unroll
                    for (int mf = 0; mf < 4; mf++) {
                        wmma::mma_sync(acc[mf][nf], afb[s & 1][mf], bfp[nf & 1], acc[mf][nf]);
                    }
                }
            }
        }
    }

    // ---- staged epilogues (all paths) ----
    __pipeline_wait_prior(0);
    __syncthreads();
    float* ws = reinterpret_cast<float*>(dynbuf) + warp * STAGE_FLOATS_PER_WARP;

    if (EPI == 1) {
        __half* Ch = hbuf(cId) + cOff + bz * strC;
#pragma unroll
        for (int mf = 0; mf < 4; mf++) {
#pragma unroll
            for (int nf = 0; nf < 4; nf++) {
                __syncwarp();
                wmma::store_matrix_sync(ws, acc[mf][nf], 20, wmma::mem_row_major);
                __syncwarp();
                int r0 = row0 + wm * 64 + mf * 16;
                int c0 = col0 + wn * 64 + nf * 16;
#pragma unroll
                for (int e = 0; e < 4; e++) {
                    int idx = lane * 4 + e;        // 0..127
                    int r = idx >> 3;              // 0..15
                    int c2 = idx & 7;              // 0..7
                    float f0 = ws[r * 20 + c2 * 2];
                    float f1 = ws[r * 20 + c2 * 2 + 1];
                    if (SCALEROW) {
                        float iv = 1.0f / g_sum[bz * Ss + r0 + r];
                        f0 *= iv;
                        f1 *= iv;
                    }
                    *reinterpret_cast<__half2*>(&Ch[(long long)(r0 + r) * ldc + c0 + c2 * 2]) =
                        __floats2half2_rn(f0, f1);
                }
            }
        }
        return;
    }

    if (EPI == 3) {
        // scores: write exp(score/32) with causal mask, fp16; fused atomic
        // per-row partial sums into g_sum. Each lane's 4 elements all lie in
        // row (lane>>1) of the fragment, so one shfl pairs the two lanes of
        // a row and the even lane issues a single atomicAdd.
        __half* Ch = hbuf(cId) + cOff + bz * strC;
        const float scl = 0.03125f;   // 1/sqrt(1024)
#pragma unroll
        for (int mf = 0; mf < 4; mf++) {
#pragma unroll
            for (int nf = 0; nf < 4; nf++) {
                __syncwarp();
                wmma::store_matrix_sync(ws, acc[mf][nf], 20, wmma::mem_row_major);
                __syncwarp();
                int r0 = row0 + wm * 64 + mf * 16;
                int c0 = col0 + wn * 64 + nf * 16;
                float lsum = 0.0f;
                int gr = r0 + (lane >> 1);
#pragma unroll
                for (int e = 0; e < 4; e++) {
                    int idx = lane * 4 + e;
                    int r = idx >> 3;
                    int c2 = idx & 7;
                    int gc = c0 + c2 * 2;
                    float f0 = ws[r * 20 + c2 * 2];
                    float f1 = ws[r * 20 + c2 * 2 + 1];
                    float e0 = (gc <= gr) ? __expf(f0 * scl) : 0.0f;
                    float e1 = (gc + 1 <= gr) ? __expf(f1 * scl) : 0.0f;
                    lsum += e0 + e1;
                    *reinterpret_cast<__half2*>(&Ch[(long long)gr * ldc + gc]) =
                        __floats2half2_rn(e0, e1);
                }
                lsum += __shfl_down_sync(0xffffffffu, lsum, 1);
                if ((lane & 1) == 0) {
                    atomicAdd(&g_sum[bz * Ss + gr], lsum);
                }
            }
        }
        return;
    }

    // EPI == 2: fp32 store with fused bias
    {
        float* Cp = extC + bz * strC;
#pragma unroll
        for (int mf = 0; mf < 4; mf++) {
#pragma unroll
            for (int nf = 0; nf < 4; nf++) {
                __syncwarp();
                wmma::store_matrix_sync(ws, acc[mf][nf], 20, wmma::mem_row_major);
                __syncwarp();
                int r0 = row0 + wm * 64 + mf * 16;
                int c0 = col0 + wn * 64 + nf * 16;
#pragma unroll
                for (int e = 0; e < 8; e++) {
                    int idx = lane + e * 32;       // 0..255
                    int r = idx >> 4;              // 0..15
                    int c = idx & 15;              // 0..15
                    Cp[(long long)(r0 + r) * ldc + c0 + c] = ws[r * 20 + c] + bias[c0 + c];
                }
            }
        }
    }
}

// standalone GEMM launches (QK proj / ctx / out)
template <int EPI, bool KLIM, bool BNN, bool SCALEROW>
__global__ void __launch_bounds__(128, 2)
hgemm_kernel(int aId, long long aOff, int bId, long long bOff,
             int cId, long long cOff, float* extC, const float* bias,
             int K, int lda, int ldb, int ldc,
             long long strA, long long strB, long long strC)
{
    extern __shared__ __align__(16) char dynbuf[];
    hgemm_body<EPI, KLIM, BNN, SCALEROW>(blockIdx.y * TBM, blockIdx.x * TBN, blockIdx.z,
                                         aId, aOff, bId, bOff, cId, cOff, extC, bias,
                                         K, lda, ldb, ldc, strA, strB, strC, dynbuf);
}

// fused launch: z<4 -> causal scores tiles (exp + atomic rowsum epilogue);
//               z==4 -> V projection tiles
__global__ void __launch_bounds__(128, 2)
fused_sv_kernel()
{
    extern __shared__ __align__(16) char dynbuf[];
    const long long sQ3 = (long long)Ss * 3 * Dd;
    const long long sAT = (long long)Ss * Ss;

    if (blockIdx.z < 4) {
        if (blockIdx.y >= (unsigned)(Ss / TBM)) return;
        const int row0 = blockIdx.y * TBM;
        const int col0 = blockIdx.x * TBN;
        if (col0 > row0 + TBM - 1) return;          // causal tile skip
        hgemm_body<3, false, false, false>(row0, col0, (long long)blockIdx.z,
                                           3, 0, 3, Dd, 4, 0, (float*)0, (const float*)0,
                                           Dd, 3 * Dd, 3 * Dd, Ss, sQ3, sQ3, sAT, dynbuf);
    } else {
        // V projection: inp * Wv^T -> qkv cols [2048, 3072)
        if (blockIdx.x >= (unsigned)(Dd / TBN)) return;
        hgemm_body<1, false, false, false>(blockIdx.y * TBM, blockIdx.x * TBN, 0,
                                           0, 0, 1, (long long)2 * Dd * Dd,
                                           3, (long long)2 * Dd, (float*)0, (const float*)0,
                                           Dd, Dd, Dd, 3 * Dd, 0, 0, 0, dynbuf);
    }
}

// ---------------------------------------------------------------------------
// conversions / transposes
// ---------------------------------------------------------------------------
// fp32 -> fp16 input; first 32 blocks also zero g_sum (runs before scores).
__global__ void conv_inp_kernel(const float* __restrict__ in)
{
    if (blockIdx.x < 32) {
        g_sum[blockIdx.x * 256 + threadIdx.x] = 0.0f;
    }
    long long i = ((long long)blockIdx.x * 256 + threadIdx.x) * 4;
    if (i < QKV_E) {
        float4 v = *reinterpret_cast<const float4*>(in + i);
        __half2* o = reinterpret_cast<__half2*>(g_inp_h + i);
        o[0] = __floats2half2_rn(v.x, v.y);
        o[1] = __floats2half2_rn(v.z, v.w);
    }
}

// fused weight transpose: z in {0,1,2} -> g_wqkv_t slab, z==3 -> g_wo_t
__global__ void wtrans4_kernel(const float* __restrict__ w0, const float* __restrict__ w1,
                               const float* __restrict__ w2, const float* __restrict__ w3)
{
    __shared__ float t[32][33];
    const float* in;
    __half* out;
    if (blockIdx.z == 0)      { in = w0; out = g_wqkv_t; }
    else if (blockIdx.z == 1) { in = w1; out = g_wqkv_t + (long long)Dd * Dd; }
    else if (blockIdx.z == 2) { in = w2; out = g_wqkv_t + (long long)2 * Dd * Dd; }
    else                      { in = w3; out = g_wo_t; }
    int r0 = blockIdx.y * 32;
    int c0 = blockIdx.x * 32;
    for (int i = threadIdx.y; i < 32; i += 8) {
        t[i][threadIdx.x] = in[(long long)(r0 + i) * Dd + c0 + threadIdx.x];
    }
    __syncthreads();
    for (int i = threadIdx.y; i < 32; i += 8) {
        out[(long long)(c0 + i) * Dd + r0 + threadIdx.x] = __float2half(t[threadIdx.x][i]);
    }
}

// ---------------------------------------------------------------------------
extern "C" void kernel_launch(void* const* d_in, const int* in_sizes, int n_in,
                              void* d_out, int out_size)
{
    const float* inp = (const float*)d_in[0];
    const float* Wq  = (const float*)d_in[1];
    const float* Wk  = (const float*)d_in[2];
    const float* Wv  = (const float*)d_in[3];
    const float* Wo  = (const float*)d_in[4];
    const float* bo  = (const float*)d_in[5];
    float* out = (float*)d_out;

    const int M = Bb * Ss;                           // 8192
    const long long sQ3 = (long long)Ss * 3 * Dd;    // per-batch stride, qkv buffer
    const long long sQK = (long long)Ss * Dd;        // per-batch q/k/v-sized stride
    const long long sAT = (long long)Ss * Ss;        // per-batch attn stride

    cudaFuncSetAttribute(hgemm_kernel<1, false, false, false>, cudaFuncAttributeMaxDynamicSharedMemorySize, SMEM_TOTAL);
    cudaFuncSetAttribute(hgemm_kernel<1, true,  true,  true >, cudaFuncAttributeMaxDynamicSharedMemorySize, SMEM_TOTAL);
    cudaFuncSetAttribute(hgemm_kernel<2, false, false, false>, cudaFuncAttributeMaxDynamicSharedMemorySize, SMEM_TOTAL);
    cudaFuncSetAttribute(fused_sv_kernel, cudaFuncAttributeMaxDynamicSharedMemorySize, SMEM_TOTAL);

    const unsigned nConv = (unsigned)((QKV_E / 4 + 255) / 256);
    dim3 tb(32, 8);

    // fp32 -> fp16 input (also zeroes g_sum); weights transposed in one launch
    conv_inp_kernel<<<nConv, 256>>>(inp);
    dim3 tw(Dd / 32, Dd / 32, 4);
    wtrans4_kernel<<<tw, tb>>>(Wq, Wk, Wv, Wo);

    // 1) QK projection: [8192,1024] x [2048,1024]^T -> qkv cols [0,2048)
    dim3 gQK(2 * Dd / TBN, M / TBM, 1);
    hgemm_kernel<1, false, false, false><<<gQK, 128, SMEM_TOTAL>>>(
        0, 0, 1, 0, 3, 0, (float*)0, (const float*)0,
        Dd, Dd, Dd, 3 * Dd, 0, 0, 0);

    // 2) fused: scores -> masked exp fp16 + atomic row sums (z<4); V proj (z==4)
    dim3 gF(Ss / TBN, M / TBM, 5);
    fused_sv_kernel<<<gF, 128, SMEM_TOTAL>>>();

    // 3) ctx = P_unnorm * V per batch (K limited), row-normalized in epilogue
    dim3 gCtx(Dd / TBN, Ss / TBM, Bb);
    hgemm_kernel<1, true, true, true><<<gCtx, 128, SMEM_TOTAL>>>(
        4, 0, 3, 2 * Dd, 5, 0, (float*)0, (const float*)0,
        Ss, Ss, 3 * Dd, Dd, sAT, sQ3, sQK);

    // 4) out = ctx * W_o + b_o (fused bias in epilogue)
    dim3 gOut(Dd / TBN, M / TBM, 1);
    hgemm_kernel<2, false, false, false><<<gOut, 128, SMEM_TOTAL>>>(
        5, 0, 2, 0, -1, 0, out, bo,
        Dd, Dd, Dd, Dd, 0, 0, 0);
}